// round 17
// baseline (speedup 1.0000x reference)
#include <cuda_runtime.h>
#include <math.h>

#define N_CRIT  128
#define N_PAIRS 8128
#define N_TOT   (N_CRIT + N_PAIRS)   // 8256
#define N_VEC4  (N_TOT / 4)          // 2064
#define HALF    (N_VEC4 / 2)         // 1032 float4 per half-row
#define MIN_W   1e-7f
#define PREP_T  1024
#define NP4     (N_PAIRS / 4)        // 2032 float4 of wint

// Effective (constrained) weight vector: [wc_eff (128) | wint_eff (8128)]
__device__ __align__(16) float g_w[N_TOT];
__device__ float g_inv_sum;

// ---------------------------------------------------------------------------
// Prep (parallel, ~1.5us): apply constraints, build contiguous weight vector,
// compute 1/sum. One block of 1024 threads; wint loaded/stored as float4.
// (i,j) recovered from the flat pair index by triangle inversion.
// ---------------------------------------------------------------------------
__device__ __forceinline__ float prep_one(int p, const float* s_wc, float wi) {
    // p -> (i, j): p = i*(2*N-1-i)/2 + (j-i-1), 2N-1 = 255
    const float disc = sqrtf((float)(65025 - 8 * p));
    int i = (int)((255.0f - disc) * 0.5f);
    int base = i * (2 * N_CRIT - 1 - i) / 2;
    if (base > p)                        { i--; base = i * (2 * N_CRIT - 1 - i) / 2; }
    else if (p - base >= N_CRIT - 1 - i) { i++; base = i * (2 * N_CRIT - 1 - i) / 2; }
    const int j = p - base + i + 1;
    const float lo = fmaxf(-s_wc[i], -s_wc[j]);
    return fmaxf(wi, lo);
}

__global__ void __launch_bounds__(PREP_T)
choquet_prep_kernel(const float* __restrict__ wc,
                    const float* __restrict__ wint) {
    __shared__ float s_wc[N_CRIT];
    __shared__ float s_part[PREP_T / 32];
    const int t = threadIdx.x;

    if (t < N_CRIT) {
        float wce = wc[t];
        if (wce < 0.f) wce = MIN_W;
        s_wc[t] = wce;
        g_w[t]  = wce;
    }
    __syncthreads();

    float sum = (t < N_CRIT) ? s_wc[t] : 0.f;

    const float4* __restrict__ wi4 = reinterpret_cast<const float4*>(wint);
    float4* __restrict__ gw4 = reinterpret_cast<float4*>(g_w + N_CRIT);

    // NP4 = 2032 float4: round 0 covers idx t, round 1 covers idx 1024+t (<2032)
    #pragma unroll
    for (int k = 0; k < 2; k++) {
        const int idx = k * PREP_T + t;
        if (idx < NP4) {
            const float4 w = wi4[idx];
            const int p = idx * 4;
            float4 v;
            v.x = prep_one(p + 0, s_wc, w.x);
            v.y = prep_one(p + 1, s_wc, w.y);
            v.z = prep_one(p + 2, s_wc, w.z);
            v.w = prep_one(p + 3, s_wc, w.w);
            gw4[idx] = v;
            sum += (v.x + v.y) + (v.z + v.w);
        }
    }

    #pragma unroll
    for (int off = 16; off > 0; off >>= 1)
        sum += __shfl_xor_sync(0xFFFFFFFFu, sum, off);
    if ((t & 31) == 0) s_part[t >> 5] = sum;
    __syncthreads();
    if (t < 32) {
        float v = (t < PREP_T / 32) ? s_part[t] : 0.f;
        #pragma unroll
        for (int off = 16; off > 0; off >>= 1)
            v += __shfl_xor_sync(0xFFFFFFFFu, v, off);
        if (t == 0) g_inv_sum = 1.0f / v;
    }
}

// ---------------------------------------------------------------------------
// GEMV: 64-thread blocks (2 warps), one row per block, half-row (1032 float4)
// per warp. 32 blocks/SM (residency cap), narrowest barrier, 32 independent
// row-streams per SM. Strided float4 loads, unroll 4, single acc chain.
// smem reduce across the 2 warps. Epilogue: sigmoid(acc * inv_sum - thr).
// ---------------------------------------------------------------------------
__global__ void __launch_bounds__(64, 32)
choquet_gemv_kernel(const float* __restrict__ x,
                    const float* __restrict__ thr,
                    float* __restrict__ out,
                    int rows) {
    __shared__ float s_part[2];

    const int warp = threadIdx.x >> 5;     // 0..1: half index within row
    const int lane = threadIdx.x & 31;
    const int r = blockIdx.x;               // one row per block

    const float4* __restrict__ xr = reinterpret_cast<const float4*>(
        x + (size_t)r * N_TOT);
    const float4* __restrict__ w4 = reinterpret_cast<const float4*>(g_w);

    const int base = warp * HALF;            // 0 or 1032

    float acc = 0.f;
    // HALF = 1032 = 32*32 + 8
    #pragma unroll 4
    for (int k = 0; k < 32; k++) {
        const int i = base + k * 32 + lane;
        const float4 a = xr[i];
        const float4 b = w4[i];
        acc = fmaf(a.x, b.x, acc);
        acc = fmaf(a.y, b.y, acc);
        acc = fmaf(a.z, b.z, acc);
        acc = fmaf(a.w, b.w, acc);
    }
    if (lane < 8) {
        const int i = base + 1024 + lane;
        const float4 a = xr[i];
        const float4 b = w4[i];
        acc = fmaf(a.x, b.x, acc);
        acc = fmaf(a.y, b.y, acc);
        acc = fmaf(a.z, b.z, acc);
        acc = fmaf(a.w, b.w, acc);
    }

    // Warp reduction
    #pragma unroll
    for (int off = 16; off > 0; off >>= 1)
        acc += __shfl_xor_sync(0xFFFFFFFFu, acc, off);
    if (lane == 0) s_part[warp] = acc;
    __syncthreads();

    // Thread 0 finalizes the row
    if (threadIdx.x == 0) {
        const float tot = s_part[0] + s_part[1];
        const float s = fmaf(tot, g_inv_sum, -thr[0]);
        out[r] = 1.0f / (1.0f + __expf(-s));
    }
}

extern "C" void kernel_launch(void* const* d_in, const int* in_sizes, int n_in,
                              void* d_out, int out_size) {
    const float* x    = (const float*)d_in[0];
    const float* wc   = (const float*)d_in[1];
    const float* wint = (const float*)d_in[2];
    const float* thr  = (const float*)d_in[3];
    float* out = (float*)d_out;

    const int rows = in_sizes[0] / N_TOT;

    choquet_prep_kernel<<<1, PREP_T>>>(wc, wint);

    choquet_gemv_kernel<<<rows, 64>>>(x, thr, out, rows);  // 1 row per block
}